// round 8
// baseline (speedup 1.0000x reference)
#include <cuda_runtime.h>
#include <cuda_fp16.h>

#define BSZ  4
#define NDIM 512
#define MDIM 512
#define HDIM 128
#define K2   (HDIM / 2)   // 64 half2 per row

// ---------------- device scratch (no allocs allowed) ----------------
// Half2 slot h: s = h&3. Slots s>=2 hold PRE-TANH'd values (identity path, 1/2),
// slots s<2 hold raw projections (MUFU tanh in score kernel, 1/2).
__device__ __half2 gh_A[BSZ * NDIM * K2];
__device__ __half2 gh_C[BSZ * MDIM * K2];

__device__ __forceinline__ float ftanh(float x) {
    float y;
    asm("tanh.approx.f32 %0, %1;" : "=f"(y) : "f"(x));
    return y;
}

// ---------------- kernel 1: projection GEMM -> routed half2 output ----------
__global__ __launch_bounds__(256) void proj_kernel(
    const float* __restrict__ first,
    const float* __restrict__ second,
    const float4* __restrict__ Wc4,   // W_concat as float4, row stride 64
    const float* __restrict__ bias)   // b_concat
{
    __shared__ float4 WsE[64 * 17];   // even cols: [p][f(16)+pad]
    __shared__ float4 WsO[64 * 17];   // odd  cols

    const int half = blockIdx.y;
    const float4* __restrict__ X4 = (const float4*)(half ? second : first);
    __half2* __restrict__ Out = half ? gh_C : gh_A;

    const int row0 = blockIdx.x * 32;
    const int tid  = threadIdx.x;
    const int warp = tid >> 5;
    const int lane = tid & 31;

    float acc[4][4];
#pragma unroll
    for (int r = 0; r < 4; ++r)
#pragma unroll
        for (int g = 0; g < 4; ++g) acc[r][g] = 0.f;

#pragma unroll
    for (int chunk = 0; chunk < 2; ++chunk) {
        if (chunk) __syncthreads();
#pragma unroll
        for (int it = 0; it < 8; ++it) {
            int idx = tid + it * 256;          // 0..2047
            int col = idx >> 4;
            int f   = idx & 15;
            float4 v = Wc4[col * 64 + half * 32 + chunk * 16 + f];
            if (col & 1) WsO[(col >> 1) * 17 + f] = v;
            else         WsE[(col >> 1) * 17 + f] = v;
        }
        __syncthreads();

#pragma unroll
        for (int f = 0; f < 16; ++f) {
            float4 w4[4];
            w4[0] = WsE[lane * 17 + f];          // col 2l
            w4[1] = WsO[lane * 17 + f];          // col 2l+1
            w4[2] = WsE[(lane + 32) * 17 + f];   // col 2l+64
            w4[3] = WsO[(lane + 32) * 17 + f];   // col 2l+65
#pragma unroll
            for (int r = 0; r < 4; ++r) {
                float4 x = X4[(row0 + warp * 4 + r) * 32 + chunk * 16 + f];
#pragma unroll
                for (int g = 0; g < 4; ++g) {
                    acc[r][g] = fmaf(x.x, w4[g].x, acc[r][g]);
                    acc[r][g] = fmaf(x.y, w4[g].y, acc[r][g]);
                    acc[r][g] = fmaf(x.z, w4[g].z, acc[r][g]);
                    acc[r][g] = fmaf(x.w, w4[g].w, acc[r][g]);
                }
            }
        }
    }

    float b0 = 0.f, b1 = 0.f, b2 = 0.f, b3 = 0.f;
    if (half == 0) {                 // fold b_concat into A
        b0 = bias[2 * lane];      b1 = bias[2 * lane + 1];
        b2 = bias[2 * lane + 64]; b3 = bias[2 * lane + 65];
    }

    // slot routing: s = lane&3; slots s>=2 pre-tanh'd (same for lane and lane+32)
    const bool tflag = (lane & 2) != 0;
    const float CL = 0.9990234375f;  // 1 - 2^-10  (keeps denom >= 0.00195)

#pragma unroll
    for (int r = 0; r < 4; ++r) {
        int row = row0 + warp * 4 + r;
        float v0 = acc[r][0] + b0, v1 = acc[r][1] + b1;
        float v2 = acc[r][2] + b2, v3 = acc[r][3] + b3;
        if (tflag) {
            v0 = fminf(fmaxf(ftanh(v0), -CL), CL);
            v1 = fminf(fmaxf(ftanh(v1), -CL), CL);
            v2 = fminf(fmaxf(ftanh(v2), -CL), CL);
            v3 = fminf(fmaxf(ftanh(v3), -CL), CL);
        }
        Out[row * K2 + lane]      = __floats2half2_rn(v0, v1);
        Out[row * K2 + 32 + lane] = __floats2half2_rn(v2, v3);
    }
}

// ---------------- identity-path tanh: (ta+tc)/(1+ta*tc), MUFU-free ----------
// bit-trick rcp guess + 2 Newton steps, all f16x2 on FMA/ALU pipes.
__device__ __forceinline__ __half2 ident2(__half2 ta, __half2 tc) {
    const unsigned oneu = 0x3C003C00u;
    const __half2 one = *(const __half2*)&oneu;
    __half2 d = __hfma2(ta, tc, one);          // 1 + ta*tc  (>= 0.00195)
    __half2 N = __hadd2(ta, tc);
    unsigned du = *(unsigned*)&d;
    unsigned ndu = du ^ 0x80008000u;           // -d  (LOP3, alu)
    __half2 nd = *(__half2*)&ndu;
    unsigned r0u = 0x78007800u - du;           // rcp guess, err in (-12.5%, 0]
    __half2 R = *(__half2*)&r0u;
    __half2 e = __hfma2(nd, R, one);           // Newton 1
    R = __hfma2(R, e, R);
    e = __hfma2(nd, R, one);                   // Newton 2 (fused into product)
    __half2 t = __hmul2(N, R);
    return __hfma2(t, e, t);                   // N*R*(1+e)
}

// ---------------- kernel 2: fused tanh-score (50/50 MUFU/identity) ----------
__global__ __launch_bounds__(256, 4) void score_kernel(
    const float* __restrict__ Wsingle,
    const float* __restrict__ bsingle,
    float* __restrict__ out)
{
    __shared__ uint4 a4s[32][16];            // [n_local][k2]  (broadcast)
    __shared__ uint4 cs[16][33];             // [k2][m_local]  +1 pad
    __shared__ __align__(16) uint2 wh[32];   // w as half2

    const int b  = blockIdx.z;
    const int n0 = blockIdx.x * 32;
    const int m0 = blockIdx.y * 32;
    const int tid  = threadIdx.x;
    const int warp = tid >> 5;
    const int lane = tid & 31;

    const uint4* __restrict__ A4 = (const uint4*)(gh_A + (size_t)(b * NDIM + n0) * K2);
    const uint4* __restrict__ C4 = (const uint4*)(gh_C + (size_t)(b * MDIM + m0) * K2);

#pragma unroll
    for (int t = 0; t < 2; ++t) {
        int idx = tid + t * 256;
        int i  = idx >> 4;
        int f4 = idx & 15;
        a4s[i][f4] = A4[i * 16 + f4];
        cs[f4][i]  = C4[i * 16 + f4];
    }
    if (tid < 32) {
        float4 w4 = ((const float4*)Wsingle)[tid];
        __half2 h01 = __floats2half2_rn(w4.x, w4.y);
        __half2 h23 = __floats2half2_rn(w4.z, w4.w);
        wh[tid] = make_uint2(*(unsigned*)&h01, *(unsigned*)&h23);
    }
    __syncthreads();

    float accX0 = 0.f, accY0 = 0.f, accX1 = 0.f, accY1 = 0.f;
    float accX2 = 0.f, accY2 = 0.f, accX3 = 0.f, accY3 = 0.f;

#define H2(u) (*(__half2*)&(u))
#define MUFU_T(au_, cu_, out_)                                                \
    {   __half2 s_ = __hadd2(H2(au_), H2(cu_));                               \
        unsigned su_ = *(unsigned*)&s_;                                       \
        asm("tanh.approx.f16x2 %0, %0;" : "+r"(su_));                         \
        out_ = *(__half2*)&su_; }

    // Per k2: slots x,y -> MUFU tanh; slots z,w -> identity (uniform pipe mix)
#define ROW_STEP(K2I, AX, AY)                                                 \
    {   uint4 au = a4s[warp * 4 + R_][K2I];                                   \
        __half2 t0, t1, t2, t3;                                               \
        MUFU_T(au.x, cu.x, t0)                                                \
        MUFU_T(au.y, cu.y, t1)                                                \
        t2 = ident2(H2(au.z), H2(cu.z));                                      \
        t3 = ident2(H2(au.w), H2(cu.w));                                      \
        __half2 p0 = __hmul2(t0, w0);                                         \
        __half2 q0 = __hfma2(t1, w1, p0);                                     \
        __half2 p2 = __hmul2(t2, w2);                                         \
        __half2 q1 = __hfma2(t3, w3, p2);                                     \
        __half2 g  = __hadd2(q0, q1);                                         \
        AX += __low2float(g);                                                 \
        AY += __high2float(g); }

#define K2_BODY(K2I)                                                          \
    {   const uint4 cu = cs[K2I][lane];                                       \
        const uint4 wu = *(const uint4*)&wh[2 * (K2I)];                       \
        const __half2 w0 = H2(wu.x), w1 = H2(wu.y);                           \
        const __half2 w2 = H2(wu.z), w3 = H2(wu.w);                           \
        { const int R_ = 0; ROW_STEP(K2I, accX0, accY0) }                     \
        { const int R_ = 1; ROW_STEP(K2I, accX1, accY1) }                     \
        { const int R_ = 2; ROW_STEP(K2I, accX2, accY2) }                     \
        { const int R_ = 3; ROW_STEP(K2I, accX3, accY3) } }

#pragma unroll
    for (int q = 0; q < 4; ++q) {   // unroll 4: 16 independent ident chains in flight
        K2_BODY(4 * q + 0)
        K2_BODY(4 * q + 1)
        K2_BODY(4 * q + 2)
        K2_BODY(4 * q + 3)
    }
#undef K2_BODY
#undef ROW_STEP
#undef MUFU_T
#undef H2

    const float bs = bsingle[0];
    const int nbase = n0 + warp * 4;
    float* __restrict__ op = out + ((size_t)b * NDIM + nbase) * MDIM + m0 + lane;
    op[0 * MDIM] = accX0 + accY0 + bs;
    op[1 * MDIM] = accX1 + accY1 + bs;
    op[2 * MDIM] = accX2 + accY2 + bs;
    op[3 * MDIM] = accX3 + accY3 + bs;
}

// ---------------- launch ----------------
extern "C" void kernel_launch(void* const* d_in, const int* in_sizes, int n_in,
                              void* d_out, int out_size) {
    const float* first   = (const float*)d_in[0];
    const float* second  = (const float*)d_in[1];
    const float* Wconcat = (const float*)d_in[2];
    const float* bconcat = (const float*)d_in[3];
    const float* Wsingle = (const float*)d_in[4];
    const float* bsingle = (const float*)d_in[5];
    float* out = (float*)d_out;

    proj_kernel<<<dim3(2048 / 32, 2), 256>>>(first, second, (const float4*)Wconcat, bconcat);
    score_kernel<<<dim3(NDIM / 32, MDIM / 32, BSZ), 256>>>(Wsingle, bsingle, out);
}

// round 9
// speedup vs baseline: 1.0581x; 1.0581x over previous
#include <cuda_runtime.h>
#include <cuda_fp16.h>

#define BSZ  4
#define NDIM 512
#define MDIM 512
#define HDIM 128
#define K2   (HDIM / 2)   // 64 half2 per row

// ---------------- device scratch (no allocs allowed) ----------------
// Half2 slot h: j = h>>2 (uint4 index), s = h&3.
// Routing: j even -> slot s==3 pre-tanh'd; j odd -> slots s>=2 pre-tanh'd.
// (5/8 raw -> MUFU tanh in score kernel; 3/8 pre-tanh'd -> identity path)
__device__ __half2 gh_A[BSZ * NDIM * K2];
__device__ __half2 gh_C[BSZ * MDIM * K2];

__device__ __forceinline__ float ftanh(float x) {
    float y;
    asm("tanh.approx.f32 %0, %1;" : "=f"(y) : "f"(x));
    return y;
}

// ---------------- kernel 1: projection GEMM -> routed half2 output ----------
__global__ __launch_bounds__(256) void proj_kernel(
    const float* __restrict__ first,
    const float* __restrict__ second,
    const float4* __restrict__ Wc4,   // W_concat as float4, row stride 64
    const float* __restrict__ bias)   // b_concat
{
    __shared__ float4 WsE[64 * 17];   // even cols: [p][f(16)+pad]
    __shared__ float4 WsO[64 * 17];   // odd  cols

    const int half = blockIdx.y;
    const float4* __restrict__ X4 = (const float4*)(half ? second : first);
    __half2* __restrict__ Out = half ? gh_C : gh_A;

    const int row0 = blockIdx.x * 32;
    const int tid  = threadIdx.x;
    const int warp = tid >> 5;
    const int lane = tid & 31;

    float acc[4][4];
#pragma unroll
    for (int r = 0; r < 4; ++r)
#pragma unroll
        for (int g = 0; g < 4; ++g) acc[r][g] = 0.f;

#pragma unroll
    for (int chunk = 0; chunk < 2; ++chunk) {
        if (chunk) __syncthreads();
#pragma unroll
        for (int it = 0; it < 8; ++it) {
            int idx = tid + it * 256;          // 0..2047
            int col = idx >> 4;
            int f   = idx & 15;
            float4 v = Wc4[col * 64 + half * 32 + chunk * 16 + f];
            if (col & 1) WsO[(col >> 1) * 17 + f] = v;
            else         WsE[(col >> 1) * 17 + f] = v;
        }
        __syncthreads();

#pragma unroll
        for (int f = 0; f < 16; ++f) {
            float4 w4[4];
            w4[0] = WsE[lane * 17 + f];          // col 2l
            w4[1] = WsO[lane * 17 + f];          // col 2l+1
            w4[2] = WsE[(lane + 32) * 17 + f];   // col 2l+64
            w4[3] = WsO[(lane + 32) * 17 + f];   // col 2l+65
#pragma unroll
            for (int r = 0; r < 4; ++r) {
                float4 x = X4[(row0 + warp * 4 + r) * 32 + chunk * 16 + f];
#pragma unroll
                for (int g = 0; g < 4; ++g) {
                    acc[r][g] = fmaf(x.x, w4[g].x, acc[r][g]);
                    acc[r][g] = fmaf(x.y, w4[g].y, acc[r][g]);
                    acc[r][g] = fmaf(x.z, w4[g].z, acc[r][g]);
                    acc[r][g] = fmaf(x.w, w4[g].w, acc[r][g]);
                }
            }
        }
    }

    float b0 = 0.f, b1 = 0.f, b2 = 0.f, b3 = 0.f;
    if (half == 0) {                 // fold b_concat into A
        b0 = bias[2 * lane];      b1 = bias[2 * lane + 1];
        b2 = bias[2 * lane + 64]; b3 = bias[2 * lane + 65];
    }

    // routing flag: h1 = lane, h2 = lane+32 -> same (j parity, s)
    const int j = lane >> 2, s = lane & 3;
    const bool tflag = (j & 1) ? (s >= 2) : (s == 3);
    const float CL = 0.9990234375f;  // 1 - 2^-10  (keeps denom >= 0.00195)

#pragma unroll
    for (int r = 0; r < 4; ++r) {
        int row = row0 + warp * 4 + r;
        float v0 = acc[r][0] + b0, v1 = acc[r][1] + b1;
        float v2 = acc[r][2] + b2, v3 = acc[r][3] + b3;
        if (tflag) {
            v0 = fminf(fmaxf(ftanh(v0), -CL), CL);
            v1 = fminf(fmaxf(ftanh(v1), -CL), CL);
            v2 = fminf(fmaxf(ftanh(v2), -CL), CL);
            v3 = fminf(fmaxf(ftanh(v3), -CL), CL);
        }
        Out[row * K2 + lane]      = __floats2half2_rn(v0, v1);
        Out[row * K2 + 32 + lane] = __floats2half2_rn(v2, v3);
    }
}

// ---------------- identity-path tanh: (ta+tc)/(1+ta*tc), MUFU-free ----------
__device__ __forceinline__ __half2 ident2(__half2 ta, __half2 tc) {
    const unsigned oneu = 0x3C003C00u;
    const __half2 one = *(const __half2*)&oneu;
    __half2 d = __hfma2(ta, tc, one);          // 1 + ta*tc  (>= 0.00195)
    __half2 N = __hadd2(ta, tc);
    unsigned du = *(unsigned*)&d;
    unsigned ndu = du ^ 0x80008000u;           // -d  (LOP3, alu)
    __half2 nd = *(__half2*)&ndu;
    unsigned r0u = 0x78007800u - du;           // rcp guess, err in (-12.5%, 0]
    __half2 R = *(__half2*)&r0u;
    __half2 e = __hfma2(nd, R, one);           // Newton 1
    R = __hfma2(R, e, R);
    e = __hfma2(nd, R, one);                   // Newton 2 (fused into product)
    __half2 t = __hmul2(N, R);
    return __hfma2(t, e, t);                   // N*R*(1+e)
}

// ---------------- kernel 2: fused tanh-score (5/8 MUFU, 3/8 identity) -------
__global__ __launch_bounds__(256, 5) void score_kernel(
    const float* __restrict__ Wsingle,
    const float* __restrict__ bsingle,
    float* __restrict__ out)
{
    __shared__ uint4 a4s[32][16];            // [n_local][k2]  (broadcast)
    __shared__ uint4 cs[16][33];             // [k2][m_local]  +1 pad
    __shared__ __align__(16) uint2 wh[32];   // w as half2

    const int b  = blockIdx.z;
    const int n0 = blockIdx.x * 32;
    const int m0 = blockIdx.y * 32;
    const int tid  = threadIdx.x;
    const int warp = tid >> 5;
    const int lane = tid & 31;

    const uint4* __restrict__ A4 = (const uint4*)(gh_A + (size_t)(b * NDIM + n0) * K2);
    const uint4* __restrict__ C4 = (const uint4*)(gh_C + (size_t)(b * MDIM + m0) * K2);

#pragma unroll
    for (int t = 0; t < 2; ++t) {
        int idx = tid + t * 256;
        int i  = idx >> 4;
        int f4 = idx & 15;
        a4s[i][f4] = A4[i * 16 + f4];
        cs[f4][i]  = C4[i * 16 + f4];
    }
    if (tid < 32) {
        float4 w4 = ((const float4*)Wsingle)[tid];
        __half2 h01 = __floats2half2_rn(w4.x, w4.y);
        __half2 h23 = __floats2half2_rn(w4.z, w4.w);
        wh[tid] = make_uint2(*(unsigned*)&h01, *(unsigned*)&h23);
    }
    __syncthreads();

    float acc0 = 0.f, acc1 = 0.f, acc2 = 0.f, acc3 = 0.f;

#define H2(u) (*(__half2*)&(u))
#define MUFU_T(au_, cu_, out_)                                                \
    {   __half2 s_ = __hadd2(H2(au_), H2(cu_));                               \
        unsigned su_ = *(unsigned*)&s_;                                       \
        asm("tanh.approx.f16x2 %0, %0;" : "+r"(su_));                         \
        out_ = *(__half2*)&su_; }

#define ROW_STEP(K2I, ODD, ACC)                                               \
    {   uint4 au = a4s[warp * 4 + R_][K2I];                                   \
        __half2 t0, t1, t2, t3;                                               \
        MUFU_T(au.x, cu.x, t0)                                                \
        MUFU_T(au.y, cu.y, t1)                                                \
        if (ODD) { t2 = ident2(H2(au.z), H2(cu.z)); }                         \
        else     { MUFU_T(au.z, cu.z, t2) }                                   \
        t3 = ident2(H2(au.w), H2(cu.w));                                      \
        __half2 g = __hmul2(t0, w0);                                          \
        g = __hfma2(t1, w1, g);                                               \
        g = __hfma2(t2, w2, g);                                               \
        g = __hfma2(t3, w3, g);                                               \
        ACC += __low2float(g);                                                \
        ACC += __high2float(g); }

#define K2_BODY(K2I, ODD)                                                     \
    {   const uint4 cu = cs[K2I][lane];                                       \
        const uint4 wu = *(const uint4*)&wh[2 * (K2I)];                       \
        const __half2 w0 = H2(wu.x), w1 = H2(wu.y);                           \
        const __half2 w2 = H2(wu.z), w3 = H2(wu.w);                           \
        { const int R_ = 0; ROW_STEP(K2I, ODD, acc0) }                        \
        { const int R_ = 1; ROW_STEP(K2I, ODD, acc1) }                        \
        { const int R_ = 2; ROW_STEP(K2I, ODD, acc2) }                        \
        { const int R_ = 3; ROW_STEP(K2I, ODD, acc3) } }

#pragma unroll 2
    for (int q = 0; q < 8; ++q) {
        K2_BODY(2 * q,     false)   // even k2: 3 MUFU + 1 identity
        K2_BODY(2 * q + 1, true)    // odd  k2: 2 MUFU + 2 identity
    }
#undef K2_BODY
#undef ROW_STEP
#undef MUFU_T
#undef H2

    const float bs = bsingle[0];
    const int nbase = n0 + warp * 4;
    float* __restrict__ op = out + ((size_t)b * NDIM + nbase) * MDIM + m0 + lane;
    op[0 * MDIM] = acc0 + bs;
    op[1 * MDIM] = acc1 + bs;
    op[2 * MDIM] = acc2 + bs;
    op[3 * MDIM] = acc3 + bs;
}

// ---------------- launch ----------------
extern "C" void kernel_launch(void* const* d_in, const int* in_sizes, int n_in,
                              void* d_out, int out_size) {
    const float* first   = (const float*)d_in[0];
    const float* second  = (const float*)d_in[1];
    const float* Wconcat = (const float*)d_in[2];
    const float* bconcat = (const float*)d_in[3];
    const float* Wsingle = (const float*)d_in[4];
    const float* bsingle = (const float*)d_in[5];
    float* out = (float*)d_out;

    proj_kernel<<<dim3(2048 / 32, 2), 256>>>(first, second, (const float4*)Wconcat, bconcat);
    score_kernel<<<dim3(NDIM / 32, MDIM / 32, BSZ), 256>>>(Wsingle, bsingle, out);
}

// round 10
// speedup vs baseline: 1.0590x; 1.0009x over previous
#include <cuda_runtime.h>
#include <cuda_fp16.h>

#define BSZ  4
#define NDIM 512
#define MDIM 512
#define HDIM 128
#define K2   (HDIM / 2)   // 64 half2 per row

// ---------------- device scratch (no allocs allowed) ----------------
// Half2 slot h: j = h>>2 (uint4 index), s = h&3.
// Routing: j even -> slot s==3 pre-tanh'd; j odd -> slots s>=2 pre-tanh'd.
// (5/8 raw -> MUFU tanh in score kernel; 3/8 pre-tanh'd -> identity path)
__device__ __half2 gh_A[BSZ * NDIM * K2];
__device__ __half2 gh_C[BSZ * MDIM * K2];

__device__ __forceinline__ float ftanh(float x) {
    float y;
    asm("tanh.approx.f32 %0, %1;" : "=f"(y) : "f"(x));
    return y;
}

// ---------------- kernel 1: projection GEMM -> routed half2 output ----------
__global__ __launch_bounds__(256) void proj_kernel(
    const float* __restrict__ first,
    const float* __restrict__ second,
    const float4* __restrict__ Wc4,   // W_concat as float4, row stride 64
    const float* __restrict__ bias)   // b_concat
{
    __shared__ float4 WsE[64 * 17];   // even cols: [p][f(16)+pad]
    __shared__ float4 WsO[64 * 17];   // odd  cols

    const int half = blockIdx.y;
    const float4* __restrict__ X4 = (const float4*)(half ? second : first);
    __half2* __restrict__ Out = half ? gh_C : gh_A;

    const int row0 = blockIdx.x * 32;
    const int tid  = threadIdx.x;
    const int warp = tid >> 5;
    const int lane = tid & 31;

    float acc[4][4];
#pragma unroll
    for (int r = 0; r < 4; ++r)
#pragma unroll
        for (int g = 0; g < 4; ++g) acc[r][g] = 0.f;

#pragma unroll
    for (int chunk = 0; chunk < 2; ++chunk) {
        if (chunk) __syncthreads();
#pragma unroll
        for (int it = 0; it < 8; ++it) {
            int idx = tid + it * 256;          // 0..2047
            int col = idx >> 4;
            int f   = idx & 15;
            float4 v = Wc4[col * 64 + half * 32 + chunk * 16 + f];
            if (col & 1) WsO[(col >> 1) * 17 + f] = v;
            else         WsE[(col >> 1) * 17 + f] = v;
        }
        __syncthreads();

#pragma unroll
        for (int f = 0; f < 16; ++f) {
            float4 w4[4];
            w4[0] = WsE[lane * 17 + f];          // col 2l
            w4[1] = WsO[lane * 17 + f];          // col 2l+1
            w4[2] = WsE[(lane + 32) * 17 + f];   // col 2l+64
            w4[3] = WsO[(lane + 32) * 17 + f];   // col 2l+65
#pragma unroll
            for (int r = 0; r < 4; ++r) {
                float4 x = X4[(row0 + warp * 4 + r) * 32 + chunk * 16 + f];
#pragma unroll
                for (int g = 0; g < 4; ++g) {
                    acc[r][g] = fmaf(x.x, w4[g].x, acc[r][g]);
                    acc[r][g] = fmaf(x.y, w4[g].y, acc[r][g]);
                    acc[r][g] = fmaf(x.z, w4[g].z, acc[r][g]);
                    acc[r][g] = fmaf(x.w, w4[g].w, acc[r][g]);
                }
            }
        }
    }

    float b0 = 0.f, b1 = 0.f, b2 = 0.f, b3 = 0.f;
    if (half == 0) {                 // fold b_concat into A
        b0 = bias[2 * lane];      b1 = bias[2 * lane + 1];
        b2 = bias[2 * lane + 64]; b3 = bias[2 * lane + 65];
    }

    // routing flag: h1 = lane, h2 = lane+32 -> same (j parity, s)
    const int j = lane >> 2, s = lane & 3;
    const bool tflag = (j & 1) ? (s >= 2) : (s == 3);
    const float CL = 0.9990234375f;  // 1 - 2^-10  (keeps denom >= 0.00195)

#pragma unroll
    for (int r = 0; r < 4; ++r) {
        int row = row0 + warp * 4 + r;
        float v0 = acc[r][0] + b0, v1 = acc[r][1] + b1;
        float v2 = acc[r][2] + b2, v3 = acc[r][3] + b3;
        if (tflag) {
            v0 = fminf(fmaxf(ftanh(v0), -CL), CL);
            v1 = fminf(fmaxf(ftanh(v1), -CL), CL);
            v2 = fminf(fmaxf(ftanh(v2), -CL), CL);
            v3 = fminf(fmaxf(ftanh(v3), -CL), CL);
        }
        Out[row * K2 + lane]      = __floats2half2_rn(v0, v1);
        Out[row * K2 + 32 + lane] = __floats2half2_rn(v2, v3);
    }
}

// ---------------- identity-path tanh: (ta+tc)/(1+ta*tc), MUFU-free ----------
__device__ __forceinline__ __half2 ident2(__half2 ta, __half2 tc) {
    const unsigned oneu = 0x3C003C00u;
    const __half2 one = *(const __half2*)&oneu;
    __half2 d = __hfma2(ta, tc, one);          // 1 + ta*tc  (>= 0.00195)
    __half2 N = __hadd2(ta, tc);
    unsigned du = *(unsigned*)&d;
    unsigned ndu = du ^ 0x80008000u;           // -d  (LOP3, alu)
    __half2 nd = *(__half2*)&ndu;
    unsigned r0u = 0x78007800u - du;           // rcp guess, err in (-12.5%, 0]
    __half2 R = *(__half2*)&r0u;
    __half2 e = __hfma2(nd, R, one);           // Newton 1
    R = __hfma2(R, e, R);
    e = __hfma2(nd, R, one);                   // Newton 2 (fused into product)
    __half2 t = __hmul2(N, R);
    return __hfma2(t, e, t);                   // N*R*(1+e)
}

// ---------------- kernel 2: fused tanh-score (5/8 MUFU, 3/8 identity) -------
__global__ __launch_bounds__(256, 6) void score_kernel(
    const float* __restrict__ Wsingle,
    const float* __restrict__ bsingle,
    float* __restrict__ out)
{
    __shared__ uint4 a4s[32][16];            // [n_local][k2]  (broadcast)
    __shared__ uint4 cs[16][33];             // [k2][m_local]  +1 pad
    __shared__ __align__(16) uint2 wh[32];   // w as half2

    const int b  = blockIdx.z;
    const int n0 = blockIdx.x * 32;
    const int m0 = blockIdx.y * 32;
    const int tid  = threadIdx.x;
    const int warp = tid >> 5;
    const int lane = tid & 31;

    const uint4* __restrict__ A4 = (const uint4*)(gh_A + (size_t)(b * NDIM + n0) * K2);
    const uint4* __restrict__ C4 = (const uint4*)(gh_C + (size_t)(b * MDIM + m0) * K2);

#pragma unroll
    for (int t = 0; t < 2; ++t) {
        int idx = tid + t * 256;
        int i  = idx >> 4;
        int f4 = idx & 15;
        a4s[i][f4] = A4[i * 16 + f4];
        cs[f4][i]  = C4[i * 16 + f4];
    }
    if (tid < 32) {
        float4 w4 = ((const float4*)Wsingle)[tid];
        __half2 h01 = __floats2half2_rn(w4.x, w4.y);
        __half2 h23 = __floats2half2_rn(w4.z, w4.w);
        wh[tid] = make_uint2(*(unsigned*)&h01, *(unsigned*)&h23);
    }
    __syncthreads();

    float acc0 = 0.f, acc1 = 0.f, acc2 = 0.f, acc3 = 0.f;

#define H2(u) (*(__half2*)&(u))
#define MUFU_T(au_, cu_, out_)                                                \
    {   __half2 s_ = __hadd2(H2(au_), H2(cu_));                               \
        unsigned su_ = *(unsigned*)&s_;                                       \
        asm("tanh.approx.f16x2 %0, %0;" : "+r"(su_));                         \
        out_ = *(__half2*)&su_; }

#define ROW_STEP(K2I, ODD, ACC)                                               \
    {   uint4 au = a4s[warp * 4 + R_][K2I];                                   \
        __half2 t0, t1, t2, t3;                                               \
        MUFU_T(au.x, cu.x, t0)                                                \
        MUFU_T(au.y, cu.y, t1)                                                \
        if (ODD) { t2 = ident2(H2(au.z), H2(cu.z)); }                         \
        else     { MUFU_T(au.z, cu.z, t2) }                                   \
        t3 = ident2(H2(au.w), H2(cu.w));                                      \
        __half2 g = __hmul2(t0, w0);                                          \
        g = __hfma2(t1, w1, g);                                               \
        g = __hfma2(t2, w2, g);                                               \
        g = __hfma2(t3, w3, g);                                               \
        ACC += __low2float(g);                                                \
        ACC += __high2float(g); }

#define K2_BODY(K2I, ODD)                                                     \
    {   const uint4 cu = cs[K2I][lane];                                       \
        const uint4 wu = *(const uint4*)&wh[2 * (K2I)];                       \
        const __half2 w0 = H2(wu.x), w1 = H2(wu.y);                           \
        const __half2 w2 = H2(wu.z), w3 = H2(wu.w);                           \
        { const int R_ = 0; ROW_STEP(K2I, ODD, acc0) }                        \
        { const int R_ = 1; ROW_STEP(K2I, ODD, acc1) }                        \
        { const int R_ = 2; ROW_STEP(K2I, ODD, acc2) }                        \
        { const int R_ = 3; ROW_STEP(K2I, ODD, acc3) } }

#pragma unroll 2
    for (int q = 0; q < 8; ++q) {
        K2_BODY(2 * q,     false)   // even k2: 3 MUFU + 1 identity
        K2_BODY(2 * q + 1, true)    // odd  k2: 2 MUFU + 2 identity
    }
#undef K2_BODY
#undef ROW_STEP
#undef MUFU_T
#undef H2

    const float bs = bsingle[0];
    const int nbase = n0 + warp * 4;
    float* __restrict__ op = out + ((size_t)b * NDIM + nbase) * MDIM + m0 + lane;
    op[0 * MDIM] = acc0 + bs;
    op[1 * MDIM] = acc1 + bs;
    op[2 * MDIM] = acc2 + bs;
    op[3 * MDIM] = acc3 + bs;
}

// ---------------- launch ----------------
extern "C" void kernel_launch(void* const* d_in, const int* in_sizes, int n_in,
                              void* d_out, int out_size) {
    const float* first   = (const float*)d_in[0];
    const float* second  = (const float*)d_in[1];
    const float* Wconcat = (const float*)d_in[2];
    const float* bconcat = (const float*)d_in[3];
    const float* Wsingle = (const float*)d_in[4];
    const float* bsingle = (const float*)d_in[5];
    float* out = (float*)d_out;

    proj_kernel<<<dim3(2048 / 32, 2), 256>>>(first, second, (const float4*)Wconcat, bconcat);
    score_kernel<<<dim3(NDIM / 32, MDIM / 32, BSZ), 256>>>(Wsingle, bsingle, out);
}

// round 11
// speedup vs baseline: 1.1142x; 1.0521x over previous
#include <cuda_runtime.h>
#include <cuda_fp16.h>

#define BSZ  4
#define NDIM 512
#define MDIM 512
#define HDIM 128
#define K2   (HDIM / 2)   // 64 half2 per row

// ---------------- device scratch (no allocs allowed) ----------------
// Half2 slot h: j = h>>2 (uint4 index), s = h&3.
// Routing: j even -> slot s==3 pre-tanh'd; j odd -> slots s>=2 pre-tanh'd.
// (5/8 raw -> MUFU tanh in score kernel; 3/8 pre-tanh'd -> identity path)
__device__ __half2 gh_A[BSZ * NDIM * K2];
__device__ __half2 gh_C[BSZ * MDIM * K2];

__device__ __forceinline__ float ftanh(float x) {
    float y;
    asm("tanh.approx.f32 %0, %1;" : "=f"(y) : "f"(x));
    return y;
}

// ---------------- kernel 1: projection GEMM -> routed half2 output ----------
__global__ __launch_bounds__(256) void proj_kernel(
    const float* __restrict__ first,
    const float* __restrict__ second,
    const float4* __restrict__ Wc4,   // W_concat as float4, row stride 64
    const float* __restrict__ bias)   // b_concat
{
    __shared__ float4 WsE[64 * 17];   // even cols: [p][f(16)+pad]
    __shared__ float4 WsO[64 * 17];   // odd  cols

    const int half = blockIdx.y;
    const float4* __restrict__ X4 = (const float4*)(half ? second : first);
    __half2* __restrict__ Out = half ? gh_C : gh_A;

    const int row0 = blockIdx.x * 32;
    const int tid  = threadIdx.x;
    const int warp = tid >> 5;
    const int lane = tid & 31;

    float acc[4][4];
#pragma unroll
    for (int r = 0; r < 4; ++r)
#pragma unroll
        for (int g = 0; g < 4; ++g) acc[r][g] = 0.f;

#pragma unroll
    for (int chunk = 0; chunk < 2; ++chunk) {
        if (chunk) __syncthreads();
#pragma unroll
        for (int it = 0; it < 8; ++it) {
            int idx = tid + it * 256;          // 0..2047
            int col = idx >> 4;
            int f   = idx & 15;
            float4 v = Wc4[col * 64 + half * 32 + chunk * 16 + f];
            if (col & 1) WsO[(col >> 1) * 17 + f] = v;
            else         WsE[(col >> 1) * 17 + f] = v;
        }
        __syncthreads();

#pragma unroll
        for (int f = 0; f < 16; ++f) {
            float4 w4[4];
            w4[0] = WsE[lane * 17 + f];          // col 2l
            w4[1] = WsO[lane * 17 + f];          // col 2l+1
            w4[2] = WsE[(lane + 32) * 17 + f];   // col 2l+64
            w4[3] = WsO[(lane + 32) * 17 + f];   // col 2l+65
#pragma unroll
            for (int r = 0; r < 4; ++r) {
                float4 x = X4[(row0 + warp * 4 + r) * 32 + chunk * 16 + f];
#pragma unroll
                for (int g = 0; g < 4; ++g) {
                    acc[r][g] = fmaf(x.x, w4[g].x, acc[r][g]);
                    acc[r][g] = fmaf(x.y, w4[g].y, acc[r][g]);
                    acc[r][g] = fmaf(x.z, w4[g].z, acc[r][g]);
                    acc[r][g] = fmaf(x.w, w4[g].w, acc[r][g]);
                }
            }
        }
    }

    float b0 = 0.f, b1 = 0.f, b2 = 0.f, b3 = 0.f;
    if (half == 0) {                 // fold b_concat into A
        b0 = bias[2 * lane];      b1 = bias[2 * lane + 1];
        b2 = bias[2 * lane + 64]; b3 = bias[2 * lane + 65];
    }

    // routing flag: h1 = lane, h2 = lane+32 -> same (j parity, s)
    const int j = lane >> 2, s = lane & 3;
    const bool tflag = (j & 1) ? (s >= 2) : (s == 3);
    const float CL = 0.9990234375f;  // 1 - 2^-10  (keeps denom >= 0.00195)

#pragma unroll
    for (int r = 0; r < 4; ++r) {
        int row = row0 + warp * 4 + r;
        float v0 = acc[r][0] + b0, v1 = acc[r][1] + b1;
        float v2 = acc[r][2] + b2, v3 = acc[r][3] + b3;
        if (tflag) {
            v0 = fminf(fmaxf(ftanh(v0), -CL), CL);
            v1 = fminf(fmaxf(ftanh(v1), -CL), CL);
            v2 = fminf(fmaxf(ftanh(v2), -CL), CL);
            v3 = fminf(fmaxf(ftanh(v3), -CL), CL);
        }
        Out[row * K2 + lane]      = __floats2half2_rn(v0, v1);
        Out[row * K2 + 32 + lane] = __floats2half2_rn(v2, v3);
    }
}

// ---------------- identity-path tanh: (ta+tc)/(1+ta*tc), MUFU-free ----------
__device__ __forceinline__ __half2 ident2(__half2 ta, __half2 tc) {
    const unsigned oneu = 0x3C003C00u;
    const __half2 one = *(const __half2*)&oneu;
    __half2 d = __hfma2(ta, tc, one);          // 1 + ta*tc  (>= 0.00195)
    __half2 N = __hadd2(ta, tc);
    unsigned du = *(unsigned*)&d;
    unsigned ndu = du ^ 0x80008000u;           // -d  (LOP3, alu)
    __half2 nd = *(__half2*)&ndu;
    unsigned r0u = 0x78007800u - du;           // rcp guess, err in (-12.5%, 0]
    __half2 R = *(__half2*)&r0u;
    __half2 e = __hfma2(nd, R, one);           // Newton 1
    R = __hfma2(R, e, R);
    e = __hfma2(nd, R, one);                   // Newton 2 (fused into product)
    __half2 t = __hmul2(N, R);
    return __hfma2(t, e, t);                   // N*R*(1+e)
}

// ---------------- kernel 2: fused tanh-score (5/8 MUFU, 3/8 identity) -------
// Pair-accumulate: weighted g for two k2 steps combined in f16; one F2F pair
// per 16 values (halves XU-pipe F2F traffic vs R10).
__global__ __launch_bounds__(256, 5) void score_kernel(
    const float* __restrict__ Wsingle,
    const float* __restrict__ bsingle,
    float* __restrict__ out)
{
    __shared__ uint4 a4s[32][16];            // [n_local][k2]  (broadcast)
    __shared__ uint4 cs[16][33];             // [k2][m_local]  +1 pad
    __shared__ __align__(16) uint2 wh[32];   // w as half2

    const int b  = blockIdx.z;
    const int n0 = blockIdx.x * 32;
    const int m0 = blockIdx.y * 32;
    const int tid  = threadIdx.x;
    const int warp = tid >> 5;
    const int lane = tid & 31;

    const uint4* __restrict__ A4 = (const uint4*)(gh_A + (size_t)(b * NDIM + n0) * K2);
    const uint4* __restrict__ C4 = (const uint4*)(gh_C + (size_t)(b * MDIM + m0) * K2);

#pragma unroll
    for (int t = 0; t < 2; ++t) {
        int idx = tid + t * 256;
        int i  = idx >> 4;
        int f4 = idx & 15;
        a4s[i][f4] = A4[i * 16 + f4];
        cs[f4][i]  = C4[i * 16 + f4];
    }
    if (tid < 32) {
        float4 w4 = ((const float4*)Wsingle)[tid];
        __half2 h01 = __floats2half2_rn(w4.x, w4.y);
        __half2 h23 = __floats2half2_rn(w4.z, w4.w);
        wh[tid] = make_uint2(*(unsigned*)&h01, *(unsigned*)&h23);
    }
    __syncthreads();

    float acc0 = 0.f, acc1 = 0.f, acc2 = 0.f, acc3 = 0.f;

#define H2(u) (*(__half2*)&(u))
#define MUFU_T(au_, cu_, out_)                                                \
    {   __half2 s_ = __hadd2(H2(au_), H2(cu_));                               \
        unsigned su_ = *(unsigned*)&s_;                                       \
        asm("tanh.approx.f16x2 %0, %0;" : "+r"(su_));                         \
        out_ = *(__half2*)&su_; }

    // g for one k2 step (no f32 conversion): ODD -> 2 ident slots, else 1
#define STEP_G(AU_, CU_, W0_, W1_, W2_, W3_, ODD, GOUT)                       \
    {   __half2 t0, t1, t2, t3;                                               \
        MUFU_T(AU_.x, CU_.x, t0)                                              \
        MUFU_T(AU_.y, CU_.y, t1)                                              \
        if (ODD) { t2 = ident2(H2(AU_.z), H2(CU_.z)); }                       \
        else     { MUFU_T(AU_.z, CU_.z, t2) }                                 \
        t3 = ident2(H2(AU_.w), H2(CU_.w));                                    \
        GOUT = __hmul2(t0, W0_);                                              \
        GOUT = __hfma2(t1, W1_, GOUT);                                        \
        GOUT = __hfma2(t2, W2_, GOUT);                                        \
        GOUT = __hfma2(t3, W3_, GOUT); }

#pragma unroll 4
    for (int q = 0; q < 8; ++q) {
        const int k0 = 2 * q, k1 = 2 * q + 1;
        const uint4 cu0 = cs[k0][lane];
        const uint4 cu1 = cs[k1][lane];
        const uint4 wu0 = *(const uint4*)&wh[2 * k0];
        const uint4 wu1 = *(const uint4*)&wh[2 * k1];
        const __half2 p0 = H2(wu0.x), p1 = H2(wu0.y), p2 = H2(wu0.z), p3 = H2(wu0.w);
        const __half2 q0 = H2(wu1.x), q1 = H2(wu1.y), q2 = H2(wu1.z), q3 = H2(wu1.w);

#define ROW_PAIR(R_, ACC)                                                     \
        {   uint4 au0 = a4s[warp * 4 + R_][k0];                               \
            uint4 au1 = a4s[warp * 4 + R_][k1];                               \
            __half2 g0, g1;                                                   \
            STEP_G(au0, cu0, p0, p1, p2, p3, false, g0)                       \
            STEP_G(au1, cu1, q0, q1, q2, q3, true,  g1)                       \
            __half2 G = __hadd2(g0, g1);                                      \
            ACC += __low2float(G);                                            \
            ACC += __high2float(G); }

        ROW_PAIR(0, acc0)
        ROW_PAIR(1, acc1)
        ROW_PAIR(2, acc2)
        ROW_PAIR(3, acc3)
#undef ROW_PAIR
    }
#undef STEP_G
#undef MUFU_T
#undef H2

    const float bs = bsingle[0];
    const int nbase = n0 + warp * 4;
    float* __restrict__ op = out + ((size_t)b * NDIM + nbase) * MDIM + m0 + lane;
    op[0 * MDIM] = acc0 + bs;
    op[1 * MDIM] = acc1 + bs;
    op[2 * MDIM] = acc2 + bs;
    op[3 * MDIM] = acc3 + bs;
}

// ---------------- launch ----------------
extern "C" void kernel_launch(void* const* d_in, const int* in_sizes, int n_in,
                              void* d_out, int out_size) {
    const float* first   = (const float*)d_in[0];
    const float* second  = (const float*)d_in[1];
    const float* Wconcat = (const float*)d_in[2];
    const float* bconcat = (const float*)d_in[3];
    const float* Wsingle = (const float*)d_in[4];
    const float* bsingle = (const float*)d_in[5];
    float* out = (float*)d_out;

    proj_kernel<<<dim3(2048 / 32, 2), 256>>>(first, second, (const float4*)Wconcat, bconcat);
    score_kernel<<<dim3(NDIM / 32, MDIM / 32, BSZ), 256>>>(Wsingle, bsingle, out);
}